// round 11
// baseline (speedup 1.0000x reference)
#include <cuda_runtime.h>
#include <cuda_fp16.h>
#include <math.h>

#define T_LEN 512
#define BATCH 64
#define HID   512
#define BH    (BATCH * HID)
#define WPH   520              // op0 weight pitch (halves): u32-pitch 260 ≡ 4 mod 32
#define BPH   40               // stage pitch (halves): u32-pitch 20 -> conflict-free
#define BUFH  (64 * BPH)       // 2560 halves per chunk buffer (5120 B)
#define NBUF  4                // staging depth per warp
#define PPITCH 33              // partials pitch (floats)

// ---------------------------------------------------------------------------
// Static device scratch
// ---------------------------------------------------------------------------
__device__ __align__(16) __half g_xr[(size_t)BATCH * T_LEN * HID];  // fp16 x
__device__ __align__(16) __half g_hseq[(size_t)T_LEN * BH];         // L0 hidden seq (fp16)
__device__ __align__(16) __half g_h2[2 * BH];                       // L1 hidden dbuf (fp16)
__device__ unsigned g_flag[2 * T_LEN * 64];                         // per-(layer,step,producer)

// ---------------------------------------------------------------------------
// Helpers
// ---------------------------------------------------------------------------
__device__ __forceinline__ unsigned pack2(float lo, float hi) {
    __half2 h = __floats2half2_rn(lo, hi);
    return *reinterpret_cast<unsigned*>(&h);
}

__device__ __forceinline__ void mma_m16n8k16(float c[4], const unsigned a[4], const unsigned b[2]) {
    asm volatile(
        "mma.sync.aligned.m16n8k16.row.col.f32.f16.f16.f32 "
        "{%0,%1,%2,%3}, {%4,%5,%6,%7}, {%8,%9}, {%0,%1,%2,%3};"
        : "+f"(c[0]), "+f"(c[1]), "+f"(c[2]), "+f"(c[3])
        : "r"(a[0]), "r"(a[1]), "r"(a[2]), "r"(a[3]), "r"(b[0]), "r"(b[1]));
}

// Gate-interleaved column n = 4*j + gate -> original weight row r = gate*512 + j
__device__ __forceinline__ int remap_row(int n) { return ((n & 3) << 9) | (n >> 2); }

__device__ __forceinline__ void cp_commit() {
    asm volatile("cp.async.commit_group;" ::: "memory");
}
__device__ __forceinline__ void cp_wait0() { asm volatile("cp.async.wait_group 0;" ::: "memory"); }
__device__ __forceinline__ void cp_wait1() { asm volatile("cp.async.wait_group 1;" ::: "memory"); }
__device__ __forceinline__ void cp_wait2() { asm volatile("cp.async.wait_group 2;" ::: "memory"); }
__device__ __forceinline__ void cp_wait3() { asm volatile("cp.async.wait_group 3;" ::: "memory"); }

// Warp-coalesced 8-flag wait: lanes 0..7 load 8 contiguous flag words
// (one 32B L2 request per poll), ballot. Tight spin (NO nanosleep).
__device__ __forceinline__ void spin8(const unsigned* base) {
    const int lane = threadIdx.x & 31;
    for (;;) {
        unsigned v = 1u;
        if (lane < 8)
            asm volatile("ld.acquire.gpu.global.u32 %0, [%1];"
                         : "=r"(v) : "l"(base + lane));
        if (__all_sync(0xffffffffu, v != 0u)) break;
    }
}

// Issue one warp-private 64x16(half) chunk = 64 rows x 32 B via cp.async.cg.
__device__ __forceinline__ void issue_chunk(__half* buf, const __half* __restrict__ src,
                                            size_t stride, int col0, int lane) {
#pragma unroll
    for (int i = 0; i < 4; i++) {
        int cc = lane + (i << 5);
        int row = cc >> 1, h8 = (cc & 1) << 3;
        const __half* g = src + (size_t)row * stride + col0 + h8;
        unsigned s = (unsigned)__cvta_generic_to_shared(buf + row * BPH + h8);
        asm volatile("cp.async.cg.shared.global [%0], [%1], 16;" :: "r"(s), "l"(g));
    }
}

// Load A-frags for one k16 chunk (m64 rows) from a stage buffer.
__device__ __forceinline__ void load_afr(unsigned afr[4][4], const __half* buf,
                                         int gi, int ti) {
    const unsigned* a32 = (const unsigned*)buf;   // u32 pitch = BPH/2 = 20
#pragma unroll
    for (int mt = 0; mt < 4; mt++) {
        int r = mt * 16;
        afr[mt][0] = a32[(r + gi) * 20 + ti];
        afr[mt][1] = a32[(r + gi + 8) * 20 + ti];
        afr[mt][2] = a32[(r + gi) * 20 + ti + 4];
        afr[mt][3] = a32[(r + gi + 8) * 20 + ti + 4];
    }
}

// MMA of one chunk: A-frags given, B from SMEM weights.
__device__ __forceinline__ void mma_smemB(float acc[4][4][4], const unsigned afr[4][4],
                                          const __half* sW0, int kbase, int gi, int ti) {
    const unsigned* w32 = (const unsigned*)sW0;   // u32 pitch = WPH/2 = 260
    int kb = (kbase >> 1) + ti;
#pragma unroll
    for (int nt = 0; nt < 4; nt++) {
        unsigned bfr[2];
        bfr[0] = w32[(nt * 8 + gi) * 260 + kb];
        bfr[1] = w32[(nt * 8 + gi) * 260 + kb + 4];
#pragma unroll
        for (int mt = 0; mt < 4; mt++) mma_m16n8k16(acc[mt][nt], afr[mt], bfr);
    }
}

// MMA of one chunk: A-frags given, B from registers (op1 critical path).
__device__ __forceinline__ void mma_regB(float acc[4][4][4], const unsigned afr[4][4],
                                         const unsigned breg[4][4][2], int u) {
#pragma unroll
    for (int nt = 0; nt < 4; nt++)
#pragma unroll
        for (int mt = 0; mt < 4; mt++)
            mma_m16n8k16(acc[mt][nt], afr[mt], breg[nt][u]);
}

// Prefetch x A-frags for step t directly into registers (plain LDG; latency
// hidden by a full step). Frag layout of mma.m16n8k16 A operand.
__device__ __forceinline__ void load_xfr(unsigned xfr[4][4][4], int t, int kw,
                                         int gi, int ti) {
    const size_t strideX = (size_t)T_LEN * HID;
    const __half* base = g_xr + (size_t)t * 512;
#pragma unroll
    for (int u = 0; u < 4; u++) {
#pragma unroll
        for (int mt = 0; mt < 4; mt++) {
            int r0 = mt * 16 + gi;
            const __half* p0 = base + (size_t)r0 * strideX + kw + 16 * u + 2 * ti;
            const __half* p1 = base + (size_t)(r0 + 8) * strideX + kw + 16 * u + 2 * ti;
            xfr[u][mt][0] = *(const unsigned*)p0;
            xfr[u][mt][1] = *(const unsigned*)p1;
            xfr[u][mt][2] = *(const unsigned*)(p0 + 8);
            xfr[u][mt][3] = *(const unsigned*)(p1 + 8);
        }
    }
}

__device__ __forceinline__ float fsig(float x) {
    return __fdividef(1.f, 1.f + __expf(-x));
}
__device__ __forceinline__ float ftanh(float x) {
    return 1.f - __fdividef(2.f, __expf(2.f * x) + 1.f);
}

// ---------------------------------------------------------------------------
// Fused dual-layer persistent LSTM (fp16 operands, fp32 accumulate).
// 128 blocks (64/layer), 256 threads (8 warps). Block owns 32 interleaved
// gate cols. L0: x A-frags prefetched to REGISTERS one step early; the
// critical path after h-detect is pure op1 (4 cp.async chunks + mma).
// L1: depth-4 cp.async pipeline over both h operands. Per-producer flag
// words, st.release publish, coalesced tight poll.
// ---------------------------------------------------------------------------
extern "C" __global__ void __launch_bounds__(256, 1)
lstm_fused(const float* __restrict__ Wx0, const float* __restrict__ bx0,
           const float* __restrict__ Wh0, const float* __restrict__ bh0,
           const float* __restrict__ Wx1, const float* __restrict__ bx1,
           const float* __restrict__ Wh1, const float* __restrict__ bh1,
           float* __restrict__ out) {
    extern __shared__ __half smem[];
    __half* sW0 = smem;                               // 32*WPH = 16640 halves
    __half* sStage = smem + 32 * WPH;                 // 8*NBUF*BUFH = 81920 halves
    float* sC = (float*)(sStage + 8 * NBUF * BUFH);   // 512 floats
    float* sBias = sC + 512;                          // 32 floats
    float* sP = (float*)sStage;                       // partials alias (67584B <= 163840B)

    const int tid = threadIdx.x;
    const int w = tid >> 5;
    const int lane = tid & 31;
    const int gi = lane >> 2;
    const int ti = lane & 3;
    const int layer = blockIdx.x >> 6;
    const int bslot = blockIdx.x & 63;
    const int n_blk = bslot * 32;
    const int kw = w * 64;                            // warp K-slice base (halves)

    __half* bufs[NBUF];
#pragma unroll
    for (int i = 0; i < NBUF; i++) bufs[i] = sStage + (w * NBUF + i) * BUFH;

    // op0 weight matrix -> SMEM ; op1 weight matrix -> registers
    const float* W0 = layer ? Wh1 : Wx0;   // op0: L0=x·Wx0, L1=h2·Wh1
    const float* W1 = layer ? Wx1 : Wh0;   // op1: L0=h1·Wh0, L1=h1·Wx1
    const float* bxp = layer ? bx1 : bx0;
    const float* bhp = layer ? bh1 : bh0;

    // Stage op0 weights once (remapped rows, fp16)
    for (int v = tid; v < 32 * 128; v += 256) {
        int row = v >> 7, c4 = (v & 127) * 4;
        int r = remap_row(n_blk + row);
        float4 f = *(const float4*)(W0 + (size_t)r * 512 + c4);
        __half2* d = (__half2*)(sW0 + (size_t)row * WPH + c4);
        d[0] = __floats2half2_rn(f.x, f.y);
        d[1] = __floats2half2_rn(f.z, f.w);
    }
    if (tid < 32) {
        int r = remap_row(n_blk + tid);
        sBias[tid] = bxp[r] + bhp[r];
    }
    for (int v = tid; v < 512; v += 256) sC[v] = 0.f;

    // Preload op1 B-fragments (fp16, 32 regs; constant across steps)
    unsigned breg[4][4][2];
#pragma unroll
    for (int nt = 0; nt < 4; nt++) {
        int r = remap_row(n_blk + nt * 8 + gi);
        const float* wr = W1 + (size_t)r * 512 + kw;
#pragma unroll
        for (int u = 0; u < 4; u++) {
            breg[nt][u][0] = pack2(wr[16 * u + 2 * ti], wr[16 * u + 2 * ti + 1]);
            breg[nt][u][1] = pack2(wr[16 * u + 2 * ti + 8], wr[16 * u + 2 * ti + 9]);
        }
    }

    unsigned xfr[4][4][4];   // L0 only: x A-frags for the current step
    if (layer == 0) load_xfr(xfr, 0, kw, gi, ti);
    __syncthreads();

    for (int t = 0; t < T_LEN; t++) {
        float acc[4][4][4];
#pragma unroll
        for (int a = 0; a < 4; a++)
#pragma unroll
            for (int b = 0; b < 4; b++)
#pragma unroll
                for (int c = 0; c < 4; c++) acc[a][b][c] = 0.f;

        if (layer == 0) {
            // ---- op0: x·Wx0 from registers, zero waits ----
#pragma unroll
            for (int u = 0; u < 4; u++)
                mma_smemB(acc, xfr[u], sW0, kw + 16 * u, gi, ti);
            // prefetch next step's x frags (consumed next iteration)
            if (t < T_LEN - 1) load_xfr(xfr, t + 1, kw, gi, ti);

            // ---- op1: h1_{t-1}·Wh0, the critical hop ----
            if (t > 0) {
                const __half* hsrc = g_hseq + (size_t)(t - 1) * BH;
                spin8(&g_flag[(size_t)(t - 1) * 64 + 8 * w]);
#pragma unroll
                for (int c = 0; c < 4; c++) {
                    issue_chunk(bufs[c], hsrc, HID, kw + 16 * c, lane);
                    cp_commit();
                }
#pragma unroll
                for (int i = 0; i < 4; i++) {
                    if (i == 0) cp_wait3(); else if (i == 1) cp_wait2();
                    else if (i == 2) cp_wait1(); else cp_wait0();
                    unsigned afr[4][4];
                    load_afr(afr, bufs[i], gi, ti);
                    mma_regB(acc, afr, breg, i);
                }
            }
        } else {
            // ---- op0: h2_{t-1}·Wh1 (own cohort, slack 1) ----
            const __half* src0 = g_h2 + (size_t)((t + 1) & 1) * BH;
            const __half* src1 = g_hseq + (size_t)t * BH;
            const bool v0 = (t > 0);
            if (v0) spin8(&g_flag[(size_t)(T_LEN + (t - 1)) * 64 + 8 * w]);
#pragma unroll
            for (int c = 0; c < 4; c++) {
                if (v0) issue_chunk(bufs[c], src0, HID, kw + 16 * c, lane);
                cp_commit();
            }
#pragma unroll
            for (int g = 0; g < 8; g++) {
                if (g < 5) cp_wait3(); else if (g == 5) cp_wait2();
                else if (g == 6) cp_wait1(); else cp_wait0();
                const int op = g >> 2;
                if (op == 1 || v0) {
                    unsigned afr[4][4];
                    load_afr(afr, bufs[g & 3], gi, ti);
                    if (op == 0) mma_smemB(acc, afr, sW0, kw + 16 * g, gi, ti);
                    else         mma_regB(acc, afr, breg, g & 3);
                }
                const int gn = g + 4;
                if (gn == 4) spin8(&g_flag[(size_t)t * 64 + 8 * w]);  // h1_t from L0
                if (gn < 8) {
                    issue_chunk(bufs[gn & 3], src1, HID, kw + 16 * (gn & 3), lane);
                    cp_commit();
                }
            }
        }

        __syncthreads();   // all warps done with stage bufs before partials alias

        // Write K-split partials
#pragma unroll
        for (int mt = 0; mt < 4; mt++) {
#pragma unroll
            for (int nt = 0; nt < 4; nt++) {
                int m = mt * 16 + gi;
                int n = nt * 8 + 2 * ti;
                int base = (w * 64 + m) * PPITCH + n;
                sP[base]     = acc[mt][nt][0];
                sP[base + 1] = acc[mt][nt][1];
                sP[base + 8 * PPITCH]     = acc[mt][nt][2];
                sP[base + 8 * PPITCH + 1] = acc[mt][nt][3];
            }
        }
        __syncthreads();

        // Reduce partials + bias + gate math + state update
        __half* h_out_h;
        if (layer == 0)
            h_out_h = g_hseq + (size_t)t * BH;
        else
            h_out_h = g_h2 + (size_t)(t & 1) * BH;
        const bool final_raw = (layer == 1) && (t == T_LEN - 1);

#pragma unroll
        for (int qq = 0; qq < 2; qq++) {
            int q = tid + (qq << 8);
            int b = q >> 3, j = q & 7;
            float s0 = 0.f, s1 = 0.f, s2 = 0.f, s3 = 0.f;
#pragma unroll
            for (int pw = 0; pw < 8; pw++) {
                int rb = (pw * 64 + b) * PPITCH + j * 4;
                s0 += sP[rb];
                s1 += sP[rb + 1];
                s2 += sP[rb + 2];
                s3 += sP[rb + 3];
            }
            float fg = fsig(s0 + sBias[j * 4 + 0]);
            float ig = fsig(s1 + sBias[j * 4 + 1]);
            float gg = ftanh(s2 + sBias[j * 4 + 2]);
            float og = fsig(s3 + sBias[j * 4 + 3]);
            float c = sC[b * 8 + j];
            c = fg * c + ig * gg;
            sC[b * 8 + j] = c;
            float hv = og * ftanh(c);
            int col = (n_blk >> 2) + j;
            if (final_raw) out[(size_t)b * HID + col] = hv;
            else           h_out_h[(size_t)b * HID + col] = __float2half_rn(hv);
        }

        // Publish: block-sync then ONE release store to this block's flag word.
        // (bar.sync orders all threads' stores before tid0's release store.)
        __syncthreads();
        if (tid == 0) {
            unsigned* p = &g_flag[(size_t)(layer * T_LEN + t) * 64 + bslot];
            asm volatile("st.release.gpu.global.u32 [%0], %1;"
                         :: "l"(p), "r"(1u) : "memory");
        }
    }
}

// ---------------------------------------------------------------------------
// Prep: fp16-convert x AND reset flags (2 graph nodes total)
// ---------------------------------------------------------------------------
__global__ void prep(const float4* __restrict__ x) {
    size_t i = (size_t)blockIdx.x * blockDim.x + threadIdx.x;
    if (i < 2 * T_LEN * 64) g_flag[i] = 0;
    float4 v = x[i];
    __half2* dst = (__half2*)g_xr;
    dst[i * 2]     = __floats2half2_rn(v.x, v.y);
    dst[i * 2 + 1] = __floats2half2_rn(v.z, v.w);
}

// ---------------------------------------------------------------------------
// Launch: 2 graph nodes
// ---------------------------------------------------------------------------
extern "C" void kernel_launch(void* const* d_in, const int* in_sizes, int n_in,
                              void* d_out, int out_size) {
    const float* x   = (const float*)d_in[0];
    const float* Wx0 = (const float*)d_in[1];
    const float* bx0 = (const float*)d_in[2];
    const float* Wh0 = (const float*)d_in[3];
    const float* bh0 = (const float*)d_in[4];
    const float* Wx1 = (const float*)d_in[5];
    const float* bx1 = (const float*)d_in[6];
    const float* Wh1 = (const float*)d_in[7];
    const float* bh1 = (const float*)d_in[8];

    const size_t SMEM_BYTES =
        (size_t)(32 * WPH + 8 * NBUF * BUFH) * sizeof(__half)
        + (512 + 32) * sizeof(float);
    cudaFuncSetAttribute(lstm_fused, cudaFuncAttributeMaxDynamicSharedMemorySize,
                         (int)SMEM_BYTES);

    prep<<<4096, 1024>>>((const float4*)x);
    lstm_fused<<<128, 256, SMEM_BYTES>>>(Wx0, bx0, Wh0, bh0,
                                         Wx1, bx1, Wh1, bh1, (float*)d_out);
}

// round 13
// speedup vs baseline: 1.5303x; 1.5303x over previous
#include <cuda_runtime.h>
#include <cuda_fp16.h>
#include <math.h>

#define T_LEN 512
#define BATCH 64
#define HID   512
#define BH    (BATCH * HID)
#define WPH   520              // op0 weight pitch (halves): u32-pitch 260 ≡ 4 mod 32
#define BPH   40               // stage pitch (halves): u32-pitch 20 -> conflict-free
#define BUFH  (64 * BPH)       // 2560 halves per chunk buffer (5120 B)
#define NBUF  4                // buffers per warp (bufs[2..3] double as partials)
#define PPITCH 33              // partials pitch (floats)

// ---------------------------------------------------------------------------
// Static device scratch
// ---------------------------------------------------------------------------
__device__ __align__(16) __half g_xr[(size_t)BATCH * T_LEN * HID];  // fp16 x
__device__ __align__(16) __half g_hseq[(size_t)T_LEN * BH];         // L0 hidden seq (fp16)
__device__ __align__(16) __half g_h2[2 * BH];                       // L1 hidden dbuf (fp16)
__device__ unsigned g_cnt[2 * T_LEN * 8];                           // per-(layer,step,group)

// ---------------------------------------------------------------------------
// Helpers
// ---------------------------------------------------------------------------
__device__ __forceinline__ unsigned pack2(float lo, float hi) {
    __half2 h = __floats2half2_rn(lo, hi);
    return *reinterpret_cast<unsigned*>(&h);
}

__device__ __forceinline__ void mma_m16n8k16(float c[4], const unsigned a[4], const unsigned b[2]) {
    asm volatile(
        "mma.sync.aligned.m16n8k16.row.col.f32.f16.f16.f32 "
        "{%0,%1,%2,%3}, {%4,%5,%6,%7}, {%8,%9}, {%0,%1,%2,%3};"
        : "+f"(c[0]), "+f"(c[1]), "+f"(c[2]), "+f"(c[3])
        : "r"(a[0]), "r"(a[1]), "r"(a[2]), "r"(a[3]), "r"(b[0]), "r"(b[1]));
}

// Gate-interleaved column n = 4*j + gate -> original weight row r = gate*512 + j
__device__ __forceinline__ int remap_row(int n) { return ((n & 3) << 9) | (n >> 2); }

__device__ __forceinline__ void cp_commit() {
    asm volatile("cp.async.commit_group;" ::: "memory");
}
__device__ __forceinline__ void cp_wait0() { asm volatile("cp.async.wait_group 0;" ::: "memory"); }
__device__ __forceinline__ void cp_wait1() { asm volatile("cp.async.wait_group 1;" ::: "memory"); }
__device__ __forceinline__ void cp_wait2() { asm volatile("cp.async.wait_group 2;" ::: "memory"); }
__device__ __forceinline__ void cp_wait3() { asm volatile("cp.async.wait_group 3;" ::: "memory"); }

// Per-warp acquire spin (tight; no nanosleep).
__device__ __forceinline__ void spin_ge(unsigned* p, unsigned v) {
    if ((threadIdx.x & 31) == 0) {
        unsigned x;
        do {
            asm volatile("ld.global.acquire.gpu.u32 %0, [%1];" : "=r"(x) : "l"(p));
        } while (x < v);
    }
    __syncwarp();
}

// Issue one warp-private 64x16(half) chunk = 64 rows x 32 B via cp.async.cg.
__device__ __forceinline__ void issue_chunk(__half* buf, const __half* __restrict__ src,
                                            size_t stride, int col0, int lane) {
#pragma unroll
    for (int i = 0; i < 4; i++) {
        int cc = lane + (i << 5);
        int row = cc >> 1, h8 = (cc & 1) << 3;
        const __half* g = src + (size_t)row * stride + col0 + h8;
        unsigned s = (unsigned)__cvta_generic_to_shared(buf + row * BPH + h8);
        asm volatile("cp.async.cg.shared.global [%0], [%1], 16;" :: "r"(s), "l"(g));
    }
}

// Load A-frags for one k16 chunk (m64 rows) from a stage buffer.
__device__ __forceinline__ void load_afr(unsigned afr[4][4], const __half* buf,
                                         int gi, int ti) {
    const unsigned* a32 = (const unsigned*)buf;   // u32 pitch = BPH/2 = 20
#pragma unroll
    for (int mt = 0; mt < 4; mt++) {
        int r = mt * 16;
        afr[mt][0] = a32[(r + gi) * 20 + ti];
        afr[mt][1] = a32[(r + gi + 8) * 20 + ti];
        afr[mt][2] = a32[(r + gi) * 20 + ti + 4];
        afr[mt][3] = a32[(r + gi + 8) * 20 + ti + 4];
    }
}

// MMA of one chunk: B from SMEM weights (op0 path).
__device__ __forceinline__ void mma_chunk_smemB(float acc[4][4][4], const __half* buf,
                                                const __half* sW0, int kbase,
                                                int gi, int ti) {
    unsigned afr[4][4];
    load_afr(afr, buf, gi, ti);
    const unsigned* w32 = (const unsigned*)sW0;   // u32 pitch = WPH/2 = 260
    int kb = (kbase >> 1) + ti;
#pragma unroll
    for (int nt = 0; nt < 4; nt++) {
        unsigned bfr[2];
        bfr[0] = w32[(nt * 8 + gi) * 260 + kb];
        bfr[1] = w32[(nt * 8 + gi) * 260 + kb + 4];
#pragma unroll
        for (int mt = 0; mt < 4; mt++) mma_m16n8k16(acc[mt][nt], afr[mt], bfr);
    }
}

// MMA of one chunk: B from registers (op1 / critical path).
__device__ __forceinline__ void mma_chunk_regB(float acc[4][4][4], const __half* buf,
                                               const unsigned breg[4][4][2], int u,
                                               int gi, int ti) {
    unsigned afr[4][4];
    load_afr(afr, buf, gi, ti);
#pragma unroll
    for (int nt = 0; nt < 4; nt++)
#pragma unroll
        for (int mt = 0; mt < 4; mt++)
            mma_m16n8k16(acc[mt][nt], afr[mt], breg[nt][u]);
}

__device__ __forceinline__ float fsig(float x) {
    return __fdividef(1.f, 1.f + __expf(-x));
}
__device__ __forceinline__ float ftanh(float x) {
    return 1.f - __fdividef(2.f, __expf(2.f * x) + 1.f);
}

// ---------------------------------------------------------------------------
// Fused dual-layer persistent LSTM (fp16 operands, fp32 accumulate).
// L0 carries next-step x chunks 0,1 across the step boundary in bufs[0..1];
// PARTIALS live inside each warp's own bufs[2..3] (warp-private alias, 8448B
// <= 10240B), so carried chunks are never clobbered (fixes the R11 NaN).
// Per-group counters + red.release publish + tight acquire spin (R8 winner).
// ---------------------------------------------------------------------------
extern "C" __global__ void __launch_bounds__(256, 1)
lstm_fused(const float* __restrict__ Wx0, const float* __restrict__ bx0,
           const float* __restrict__ Wh0, const float* __restrict__ bh0,
           const float* __restrict__ Wx1, const float* __restrict__ bx1,
           const float* __restrict__ Wh1, const float* __restrict__ bh1,
           float* __restrict__ out) {
    extern __shared__ __half smem[];
    __half* sW0 = smem;                               // 32*WPH = 16640 halves
    __half* sStage = smem + 32 * WPH;                 // 8*NBUF*BUFH = 81920 halves
    float* sC = (float*)(sStage + 8 * NBUF * BUFH);   // 512 floats
    float* sBias = sC + 512;                          // 32 floats

    const int tid = threadIdx.x;
    const int w = tid >> 5;
    const int lane = tid & 31;
    const int gi = lane >> 2;
    const int ti = lane & 3;
    const int layer = blockIdx.x >> 6;
    const int bslot = blockIdx.x & 63;
    const int n_blk = bslot * 32;
    const int kw = w * 64;                            // warp K-slice base (halves)
    const size_t strideX = (size_t)T_LEN * HID;

    __half* bufs[NBUF];
#pragma unroll
    for (int i = 0; i < NBUF; i++) bufs[i] = sStage + (w * NBUF + i) * BUFH;
    // Warp-private partials region: aliases this warp's bufs[2..3].
    float* myP = (float*)(sStage + (w * NBUF + 2) * BUFH);

    // op0 weight matrix -> SMEM ; op1 weight matrix -> registers
    const float* W0 = layer ? Wh1 : Wx0;   // op0: L0=x·Wx0, L1=h2·Wh1
    const float* W1 = layer ? Wx1 : Wh0;   // op1: L0=h1·Wh0, L1=h1·Wx1
    const float* bxp = layer ? bx1 : bx0;
    const float* bhp = layer ? bh1 : bh0;

    // Stage op0 weights once (remapped rows, fp16)
    for (int v = tid; v < 32 * 128; v += 256) {
        int row = v >> 7, c4 = (v & 127) * 4;
        int r = remap_row(n_blk + row);
        float4 f = *(const float4*)(W0 + (size_t)r * 512 + c4);
        __half2* d = (__half2*)(sW0 + (size_t)row * WPH + c4);
        d[0] = __floats2half2_rn(f.x, f.y);
        d[1] = __floats2half2_rn(f.z, f.w);
    }
    if (tid < 32) {
        int r = remap_row(n_blk + tid);
        sBias[tid] = bxp[r] + bhp[r];
    }
    for (int v = tid; v < 512; v += 256) sC[v] = 0.f;

    // Preload op1 B-fragments (fp16, 32 regs; constant across steps)
    unsigned breg[4][4][2];
#pragma unroll
    for (int nt = 0; nt < 4; nt++) {
        int r = remap_row(n_blk + nt * 8 + gi);
        const float* wr = W1 + (size_t)r * 512 + kw;
#pragma unroll
        for (int u = 0; u < 4; u++) {
            breg[nt][u][0] = pack2(wr[16 * u + 2 * ti], wr[16 * u + 2 * ti + 1]);
            breg[nt][u][1] = pack2(wr[16 * u + 2 * ti + 8], wr[16 * u + 2 * ti + 9]);
        }
    }
    __syncthreads();

    // L0: prime carried x chunks 0,1 of t=0
    if (layer == 0) {
        issue_chunk(bufs[0], g_xr, strideX, kw + 0, lane);
        cp_commit();
        issue_chunk(bufs[1], g_xr, strideX, kw + 16, lane);
        cp_commit();
    }

    for (int t = 0; t < T_LEN; t++) {
        float acc[4][4][4];
#pragma unroll
        for (int a = 0; a < 4; a++)
#pragma unroll
            for (int b = 0; b < 4; b++)
#pragma unroll
                for (int c = 0; c < 4; c++) acc[a][b][c] = 0.f;

        if (layer == 0) {
            const __half* xcur = g_xr + (size_t)t * 512;
            const __half* xnext = g_xr + (size_t)(t + 1) * 512;
            const __half* hsrc = g_hseq + (size_t)(t - 1) * BH;
            const bool v1 = (t > 0);
            // Step start: x chunks 2,3 (bufs[2,3] were partials last step; now free)
            issue_chunk(bufs[2], xcur, strideX, kw + 32, lane);
            cp_commit();
            issue_chunk(bufs[3], xcur, strideX, kw + 48, lane);
            cp_commit();
            // Group FIFO: [x c0, x c1 (carried), x c2, x c3, h c0..c3, x' c0, x' c1]
#pragma unroll
            for (int g = 0; g < 8; g++) {
                if (g < 7) cp_wait3(); else cp_wait2();
                if (g < 4)
                    mma_chunk_smemB(acc, bufs[g], sW0, kw + 16 * g, gi, ti);
                else if (v1)
                    mma_chunk_regB(acc, bufs[g & 3], breg, g - 4, gi, ti);
                if (g == 0 && v1)   // detect h_{t-1} right after first mma
                    spin_ge(&g_cnt[(t - 1) * 8 + w], 8u);
                if (g < 4) {
                    if (v1) issue_chunk(bufs[g], hsrc, HID, kw + 16 * g, lane);
                    cp_commit();
                } else if (g < 6) {
                    if (t < T_LEN - 1)
                        issue_chunk(bufs[g - 4], xnext, strideX, kw + 16 * (g - 4), lane);
                    cp_commit();
                }
                // g=6,7: no commits (carry x' c0,c1 outstanding into next step)
            }
        } else {
            const __half* src0 = g_h2 + (size_t)((t + 1) & 1) * BH;
            const __half* src1 = g_hseq + (size_t)t * BH;
            const bool v0 = (t > 0);
            if (v0) spin_ge(&g_cnt[(T_LEN + (t - 1)) * 8 + w], 8u);
#pragma unroll
            for (int c = 0; c < 4; c++) {
                if (v0) issue_chunk(bufs[c], src0, HID, kw + 16 * c, lane);
                cp_commit();
            }
#pragma unroll
            for (int g = 0; g < 8; g++) {
                if (g < 5) cp_wait3(); else if (g == 5) cp_wait2();
                else if (g == 6) cp_wait1(); else cp_wait0();
                if (g < 4) {
                    if (v0) mma_chunk_smemB(acc, bufs[g], sW0, kw + 16 * g, gi, ti);
                } else {
                    mma_chunk_regB(acc, bufs[g & 3], breg, g - 4, gi, ti);
                }
                const int gn = g + 4;
                if (gn == 4) spin_ge(&g_cnt[t * 8 + w], 8u);   // h1_t from L0
                if (gn < 8) {
                    issue_chunk(bufs[gn & 3], src1, HID, kw + 16 * (gn - 4), lane);
                    cp_commit();
                }
            }
        }

        // Write K-split partials into THIS warp's private region (bufs[2..3]
        // alias). In-warp ordering guarantees our mma LDS reads preceded this.
#pragma unroll
        for (int mt = 0; mt < 4; mt++) {
#pragma unroll
            for (int nt = 0; nt < 4; nt++) {
                int m = mt * 16 + gi;
                int n = nt * 8 + 2 * ti;
                int base = m * PPITCH + n;
                myP[base]     = acc[mt][nt][0];
                myP[base + 1] = acc[mt][nt][1];
                myP[base + 8 * PPITCH]     = acc[mt][nt][2];
                myP[base + 8 * PPITCH + 1] = acc[mt][nt][3];
            }
        }
        __syncthreads();   // all partials visible before cross-warp reduce

        // Reduce partials + bias + gate math + state update
        __half* h_out_h;
        if (layer == 0)
            h_out_h = g_hseq + (size_t)t * BH;
        else
            h_out_h = g_h2 + (size_t)(t & 1) * BH;
        const bool final_raw = (layer == 1) && (t == T_LEN - 1);

#pragma unroll
        for (int qq = 0; qq < 2; qq++) {
            int q = tid + (qq << 8);
            int b = q >> 3, j = q & 7;
            float s0 = 0.f, s1 = 0.f, s2 = 0.f, s3 = 0.f;
#pragma unroll
            for (int pw = 0; pw < 8; pw++) {
                const float* pp = (const float*)(sStage + (pw * NBUF + 2) * BUFH);
                int rb = b * PPITCH + j * 4;
                s0 += pp[rb];
                s1 += pp[rb + 1];
                s2 += pp[rb + 2];
                s3 += pp[rb + 3];
            }
            float fg = fsig(s0 + sBias[j * 4 + 0]);
            float ig = fsig(s1 + sBias[j * 4 + 1]);
            float gg = ftanh(s2 + sBias[j * 4 + 2]);
            float og = fsig(s3 + sBias[j * 4 + 3]);
            float c = sC[b * 8 + j];
            c = fg * c + ig * gg;
            sC[b * 8 + j] = c;
            float hv = og * ftanh(c);
            int col = (n_blk >> 2) + j;
            if (final_raw) out[(size_t)b * HID + col] = hv;
            else           h_out_h[(size_t)b * HID + col] = __float2half_rn(hv);
        }

        // Publish: block-sync (also protects partials region reuse) then
        // ONE release-reduction.
        __syncthreads();
        if (tid == 0) {
            unsigned* p = &g_cnt[((layer * T_LEN) + t) * 8 + (bslot >> 3)];
            asm volatile("red.release.gpu.global.add.u32 [%0], %1;"
                         :: "l"(p), "r"(1u) : "memory");
        }
    }
}

// ---------------------------------------------------------------------------
// Prep: fp16-convert x AND reset counters (2 graph nodes total)
// ---------------------------------------------------------------------------
__global__ void prep(const float4* __restrict__ x) {
    size_t i = (size_t)blockIdx.x * blockDim.x + threadIdx.x;
    if (i < 2 * T_LEN * 8) g_cnt[i] = 0;
    float4 v = x[i];
    __half2* dst = (__half2*)g_xr;
    dst[i * 2]     = __floats2half2_rn(v.x, v.y);
    dst[i * 2 + 1] = __floats2half2_rn(v.z, v.w);
}

// ---------------------------------------------------------------------------
// Launch: 2 graph nodes
// ---------------------------------------------------------------------------
extern "C" void kernel_launch(void* const* d_in, const int* in_sizes, int n_in,
                              void* d_out, int out_size) {
    const float* x   = (const float*)d_in[0];
    const float* Wx0 = (const float*)d_in[1];
    const float* bx0 = (const float*)d_in[2];
    const float* Wh0 = (const float*)d_in[3];
    const float* bh0 = (const float*)d_in[4];
    const float* Wx1 = (const float*)d_in[5];
    const float* bx1 = (const float*)d_in[6];
    const float* Wh1 = (const float*)d_in[7];
    const float* bh1 = (const float*)d_in[8];

    const size_t SMEM_BYTES =
        (size_t)(32 * WPH + 8 * NBUF * BUFH) * sizeof(__half)
        + (512 + 32) * sizeof(float);
    cudaFuncSetAttribute(lstm_fused, cudaFuncAttributeMaxDynamicSharedMemorySize,
                         (int)SMEM_BYTES);

    prep<<<4096, 1024>>>((const float4*)x);
    lstm_fused<<<128, 256, SMEM_BYTES>>>(Wx0, bx0, Wh0, bh0,
                                         Wx1, bx1, Wh1, bh1, (float*)d_out);
}

// round 14
// speedup vs baseline: 1.8097x; 1.1826x over previous
#include <cuda_runtime.h>
#include <cuda_fp16.h>
#include <math.h>

#define T_LEN 512
#define BATCH 64
#define HID   512
#define BH    (BATCH * HID)
#define WPH   520              // op0 weight pitch (halves): u32-pitch 260 ≡ 4 mod 32
#define BPH   72               // slice pitch (halves): u32-pitch 36 ≡ 4 mod 32 -> A-frag conflict-free
#define BUFH  (64 * BPH)       // 4608 halves per slice buffer (9216 B)
#define PPITCH 33              // partials pitch (floats); 64*33*4=8448B <= 9216B (aliases bufA)

// ---------------------------------------------------------------------------
// Static device scratch
// ---------------------------------------------------------------------------
__device__ __align__(16) __half g_xr[(size_t)BATCH * T_LEN * HID];  // fp16 x
__device__ __align__(16) __half g_hseq[(size_t)T_LEN * BH];         // L0 hidden seq (fp16)
__device__ __align__(16) __half g_h2[2 * BH];                       // L1 hidden dbuf (fp16)
__device__ unsigned g_cnt[2 * T_LEN * 8];                           // per-(layer,step,group)

// ---------------------------------------------------------------------------
// Helpers
// ---------------------------------------------------------------------------
__device__ __forceinline__ unsigned pack2(float lo, float hi) {
    __half2 h = __floats2half2_rn(lo, hi);
    return *reinterpret_cast<unsigned*>(&h);
}

__device__ __forceinline__ void mma_m16n8k16(float c[4], const unsigned a[4], const unsigned b[2]) {
    asm volatile(
        "mma.sync.aligned.m16n8k16.row.col.f32.f16.f16.f32 "
        "{%0,%1,%2,%3}, {%4,%5,%6,%7}, {%8,%9}, {%0,%1,%2,%3};"
        : "+f"(c[0]), "+f"(c[1]), "+f"(c[2]), "+f"(c[3])
        : "r"(a[0]), "r"(a[1]), "r"(a[2]), "r"(a[3]), "r"(b[0]), "r"(b[1]));
}

// Gate-interleaved column n = 4*j + gate -> original weight row r = gate*512 + j
__device__ __forceinline__ int remap_row(int n) { return ((n & 3) << 9) | (n >> 2); }

__device__ __forceinline__ void cp_commit() {
    asm volatile("cp.async.commit_group;" ::: "memory");
}
__device__ __forceinline__ void cp_wait0() { asm volatile("cp.async.wait_group 0;" ::: "memory"); }
__device__ __forceinline__ void cp_wait1() { asm volatile("cp.async.wait_group 1;" ::: "memory"); }

// Per-warp spin: RELAXED poll loop, then ONE acquire load to establish order.
__device__ __forceinline__ void spin_ge(unsigned* p, unsigned v) {
    if ((threadIdx.x & 31) == 0) {
        unsigned x;
        do {
            asm volatile("ld.global.relaxed.gpu.u32 %0, [%1];" : "=r"(x) : "l"(p));
        } while (x < v);
        asm volatile("ld.global.acquire.gpu.u32 %0, [%1];" : "=r"(x) : "l"(p));
    }
    __syncwarp();
}

// Issue one warp-private 64x64(half) SLICE = 64 rows x 128 B via cp.async.cg.
// 512 16B units; thread i-th unit = lane + 32i; row = unit>>3, off = (unit&7)*8h.
__device__ __forceinline__ void issue_slice(__half* buf, const __half* __restrict__ src,
                                            size_t stride, int col0, int lane) {
#pragma unroll
    for (int i = 0; i < 16; i++) {
        int unit = lane + (i << 5);
        int row = unit >> 3, off8 = (unit & 7) << 3;
        const __half* g = src + (size_t)row * stride + col0 + off8;
        unsigned s = (unsigned)__cvta_generic_to_shared(buf + row * BPH + off8);
        asm volatile("cp.async.cg.shared.global [%0], [%1], 16;" :: "r"(s), "l"(g));
    }
}

// Load A-frags for k16 unit u (0..3) of a slice buffer (u32 pitch 36).
__device__ __forceinline__ void load_afr(unsigned afr[4][4], const __half* buf, int u,
                                         int gi, int ti) {
    const unsigned* a32 = (const unsigned*)buf;
    int kb = (u << 3) + ti;
#pragma unroll
    for (int mt = 0; mt < 4; mt++) {
        int r = mt * 16;
        afr[mt][0] = a32[(r + gi) * 36 + kb];
        afr[mt][1] = a32[(r + gi + 8) * 36 + kb];
        afr[mt][2] = a32[(r + gi) * 36 + kb + 4];
        afr[mt][3] = a32[(r + gi + 8) * 36 + kb + 4];
    }
}

// op0: full slice MMA, B from SMEM weights.
__device__ __forceinline__ void mma_slice_smemB(float acc[4][4][4], const __half* buf,
                                                const __half* sW0, int kw,
                                                int gi, int ti) {
    const unsigned* w32 = (const unsigned*)sW0;   // u32 pitch 260
#pragma unroll
    for (int u = 0; u < 4; u++) {
        unsigned afr[4][4];
        load_afr(afr, buf, u, gi, ti);
        int kb = (kw >> 1) + (u << 3) + ti;
#pragma unroll
        for (int nt = 0; nt < 4; nt++) {
            unsigned bfr[2];
            bfr[0] = w32[(nt * 8 + gi) * 260 + kb];
            bfr[1] = w32[(nt * 8 + gi) * 260 + kb + 4];
#pragma unroll
            for (int mt = 0; mt < 4; mt++) mma_m16n8k16(acc[mt][nt], afr[mt], bfr);
        }
    }
}

// op1: full slice MMA, B from registers.
__device__ __forceinline__ void mma_slice_regB(float acc[4][4][4], const __half* buf,
                                               const unsigned breg[4][4][2],
                                               int gi, int ti) {
#pragma unroll
    for (int u = 0; u < 4; u++) {
        unsigned afr[4][4];
        load_afr(afr, buf, u, gi, ti);
#pragma unroll
        for (int nt = 0; nt < 4; nt++)
#pragma unroll
            for (int mt = 0; mt < 4; mt++)
                mma_m16n8k16(acc[mt][nt], afr[mt], breg[nt][u]);
    }
}

__device__ __forceinline__ float fsig(float x) {
    return __fdividef(1.f, 1.f + __expf(-x));
}
__device__ __forceinline__ float ftanh(float x) {
    return 1.f - __fdividef(2.f, __expf(2.f * x) + 1.f);
}

// ---------------------------------------------------------------------------
// Fused dual-layer persistent LSTM (fp16 operands, fp32 accumulate).
// ONE cp.async slice per operand per step (2 groups total): the entire h
// slice is issued immediately after detect; op0 mma hides the h fetch.
// Per-group counters + red.release publish + relaxed-poll spin.
// ---------------------------------------------------------------------------
extern "C" __global__ void __launch_bounds__(256, 1)
lstm_fused(const float* __restrict__ Wx0, const float* __restrict__ bx0,
           const float* __restrict__ Wh0, const float* __restrict__ bh0,
           const float* __restrict__ Wx1, const float* __restrict__ bx1,
           const float* __restrict__ Wh1, const float* __restrict__ bh1,
           float* __restrict__ out) {
    extern __shared__ __half smem[];
    __half* sW0 = smem;                               // 32*WPH = 16640 halves
    __half* sStage = smem + 32 * WPH;                 // 8 warps * 2 * BUFH = 73728 halves
    float* sC = (float*)(sStage + 16 * BUFH);         // 512 floats
    float* sBias = sC + 512;                          // 32 floats

    const int tid = threadIdx.x;
    const int w = tid >> 5;
    const int lane = tid & 31;
    const int gi = lane >> 2;
    const int ti = lane & 3;
    const int layer = blockIdx.x >> 6;
    const int bslot = blockIdx.x & 63;
    const int n_blk = bslot * 32;
    const int kw = w * 64;                            // warp K-slice base (halves)
    const size_t strideX = (size_t)T_LEN * HID;

    __half* bufA = sStage + (w * 2) * BUFH;           // op0 slice (aliased by partials)
    __half* bufB = bufA + BUFH;                       // op1 slice
    float* myP = (float*)bufA;                        // this warp's partials

    // op0 weight matrix -> SMEM ; op1 weight matrix -> registers
    const float* W0 = layer ? Wh1 : Wx0;   // op0: L0=x·Wx0, L1=h2·Wh1
    const float* W1 = layer ? Wx1 : Wh0;   // op1: L0=h1·Wh0, L1=h1·Wx1
    const float* bxp = layer ? bx1 : bx0;
    const float* bhp = layer ? bh1 : bh0;

    // Stage op0 weights once (remapped rows, fp16)
    for (int v = tid; v < 32 * 128; v += 256) {
        int row = v >> 7, c4 = (v & 127) * 4;
        int r = remap_row(n_blk + row);
        float4 f = *(const float4*)(W0 + (size_t)r * 512 + c4);
        __half2* d = (__half2*)(sW0 + (size_t)row * WPH + c4);
        d[0] = __floats2half2_rn(f.x, f.y);
        d[1] = __floats2half2_rn(f.z, f.w);
    }
    if (tid < 32) {
        int r = remap_row(n_blk + tid);
        sBias[tid] = bxp[r] + bhp[r];
    }
    for (int v = tid; v < 512; v += 256) sC[v] = 0.f;

    // Preload op1 B-fragments (fp16, 32 regs; constant across steps)
    unsigned breg[4][4][2];
#pragma unroll
    for (int nt = 0; nt < 4; nt++) {
        int r = remap_row(n_blk + nt * 8 + gi);
        const float* wr = W1 + (size_t)r * 512 + kw;
#pragma unroll
        for (int u = 0; u < 4; u++) {
            breg[nt][u][0] = pack2(wr[16 * u + 2 * ti], wr[16 * u + 2 * ti + 1]);
            breg[nt][u][1] = pack2(wr[16 * u + 2 * ti + 8], wr[16 * u + 2 * ti + 9]);
        }
    }
    __syncthreads();

    for (int t = 0; t < T_LEN; t++) {
        float acc[4][4][4];
#pragma unroll
        for (int a = 0; a < 4; a++)
#pragma unroll
            for (int b = 0; b < 4; b++)
#pragma unroll
                for (int c = 0; c < 4; c++) acc[a][b][c] = 0.f;

        bool v0, v1;
        if (layer == 0) {
            // op0 = x_t (always), op1 = h1_{t-1} (t>0)
            v0 = true; v1 = (t > 0);
            issue_slice(bufA, g_xr + (size_t)t * 512, strideX, kw, lane);
            cp_commit();                                   // group X
            if (v1) {
                spin_ge(&g_cnt[(t - 1) * 8 + w], 8u);      // detect h1_{t-1}
                issue_slice(bufB, g_hseq + (size_t)(t - 1) * BH, HID, kw, lane);
            }
            cp_commit();                                   // group H (may be empty)
        } else {
            // op0 = h2_{t-1} (t>0), op1 = h1_t (always)
            v0 = (t > 0); v1 = true;
            if (v0) {
                spin_ge(&g_cnt[(T_LEN + (t - 1)) * 8 + w], 8u);
                issue_slice(bufA, g_h2 + (size_t)((t + 1) & 1) * BH, HID, kw, lane);
            }
            cp_commit();                                   // group A (may be empty)
            spin_ge(&g_cnt[t * 8 + w], 8u);                // detect h1_t
            issue_slice(bufB, g_hseq + (size_t)t * BH, HID, kw, lane);
            cp_commit();                                   // group B
        }

        cp_wait1();     // op0 slice resident
        if (v0) mma_slice_smemB(acc, bufA, sW0, kw, gi, ti);
        cp_wait0();     // op1 slice resident
        if (v1) mma_slice_regB(acc, bufB, breg, gi, ti);

        // Write K-split partials into this warp's private region (bufA alias;
        // in-warp ordering: our mma LDS reads of bufA precede these stores).
#pragma unroll
        for (int mt = 0; mt < 4; mt++) {
#pragma unroll
            for (int nt = 0; nt < 4; nt++) {
                int m = mt * 16 + gi;
                int n = nt * 8 + 2 * ti;
                int base = m * PPITCH + n;
                myP[base]     = acc[mt][nt][0];
                myP[base + 1] = acc[mt][nt][1];
                myP[base + 8 * PPITCH]     = acc[mt][nt][2];
                myP[base + 8 * PPITCH + 1] = acc[mt][nt][3];
            }
        }
        __syncthreads();   // all partials visible before cross-warp reduce

        // Reduce partials + bias + gate math + state update
        __half* h_out_h;
        if (layer == 0)
            h_out_h = g_hseq + (size_t)t * BH;
        else
            h_out_h = g_h2 + (size_t)(t & 1) * BH;
        const bool final_raw = (layer == 1) && (t == T_LEN - 1);

#pragma unroll
        for (int qq = 0; qq < 2; qq++) {
            int q = tid + (qq << 8);
            int b = q >> 3, j = q & 7;
            float s0 = 0.f, s1 = 0.f, s2 = 0.f, s3 = 0.f;
#pragma unroll
            for (int pw = 0; pw < 8; pw++) {
                const float* pp = (const float*)(sStage + (pw * 2) * BUFH);
                int rb = b * PPITCH + j * 4;
                s0 += pp[rb];
                s1 += pp[rb + 1];
                s2 += pp[rb + 2];
                s3 += pp[rb + 3];
            }
            float fg = fsig(s0 + sBias[j * 4 + 0]);
            float ig = fsig(s1 + sBias[j * 4 + 1]);
            float gg = ftanh(s2 + sBias[j * 4 + 2]);
            float og = fsig(s3 + sBias[j * 4 + 3]);
            float c = sC[b * 8 + j];
            c = fg * c + ig * gg;
            sC[b * 8 + j] = c;
            float hv = og * ftanh(c);
            int col = (n_blk >> 2) + j;
            if (final_raw) out[(size_t)b * HID + col] = hv;
            else           h_out_h[(size_t)b * HID + col] = __float2half_rn(hv);
        }

        // Publish: block-sync (also protects partials/bufA reuse) then ONE
        // release-reduction.
        __syncthreads();
        if (tid == 0) {
            unsigned* p = &g_cnt[((layer * T_LEN) + t) * 8 + (bslot >> 3)];
            asm volatile("red.release.gpu.global.add.u32 [%0], %1;"
                         :: "l"(p), "r"(1u) : "memory");
        }
    }
}

// ---------------------------------------------------------------------------
// Prep: fp16-convert x AND reset counters (2 graph nodes total)
// ---------------------------------------------------------------------------
__global__ void prep(const float4* __restrict__ x) {
    size_t i = (size_t)blockIdx.x * blockDim.x + threadIdx.x;
    if (i < 2 * T_LEN * 8) g_cnt[i] = 0;
    float4 v = x[i];
    __half2* dst = (__half2*)g_xr;
    dst[i * 2]     = __floats2half2_rn(v.x, v.y);
    dst[i * 2 + 1] = __floats2half2_rn(v.z, v.w);
}

// ---------------------------------------------------------------------------
// Launch: 2 graph nodes
// ---------------------------------------------------------------------------
extern "C" void kernel_launch(void* const* d_in, const int* in_sizes, int n_in,
                              void* d_out, int out_size) {
    const float* x   = (const float*)d_in[0];
    const float* Wx0 = (const float*)d_in[1];
    const float* bx0 = (const float*)d_in[2];
    const float* Wh0 = (const float*)d_in[3];
    const float* bh0 = (const float*)d_in[4];
    const float* Wx1 = (const float*)d_in[5];
    const float* bx1 = (const float*)d_in[6];
    const float* Wh1 = (const float*)d_in[7];
    const float* bh1 = (const float*)d_in[8];

    const size_t SMEM_BYTES =
        (size_t)(32 * WPH + 16 * BUFH) * sizeof(__half)
        + (512 + 32) * sizeof(float);
    cudaFuncSetAttribute(lstm_fused, cudaFuncAttributeMaxDynamicSharedMemorySize,
                         (int)SMEM_BYTES);

    prep<<<4096, 1024>>>((const float4*)x);
    lstm_fused<<<128, 256, SMEM_BYTES>>>(Wx0, bx0, Wh0, bh0,
                                         Wx1, bx1, Wh1, bh1, (float*)d_out);
}